// round 3
// baseline (speedup 1.0000x reference)
#include <cuda_runtime.h>

#define PITCH 129                                   // float2 pitch
#define NF_MAX 2850                                 // >= 2821 masked frequencies
#define SMEM_BYTES (128 * PITCH * sizeof(float2))   // 132096 B

// ---------------- device scratch ------------------------------------------------
__device__ float2 g_E[128];                         // exp(-2*pi*i*k/128)
__device__ int    g_maskUV[NF_MAX];
__device__ int    g_conjRank[NF_MAX];
__device__ float4 g_Xf4[(size_t)NF_MAX * 512];      // [f][i*16+b] /2  masked X spectrum
__device__ float4 g_Yf4[(size_t)NF_MAX * 512];      // [f][b*64+o] /2  masked Y spectrum
#define g_Xf ((float2*)g_Xf4)
#define g_Yf ((float2*)g_Yf4)

__device__ __forceinline__ int brev7(int x) { return (int)(__brev((unsigned)x) >> 25); }
__device__ __forceinline__ float2 cadd(float2 a, float2 b){ return make_float2(a.x+b.x, a.y+b.y); }
__device__ __forceinline__ float2 csub(float2 a, float2 b){ return make_float2(a.x-b.x, a.y-b.y); }
__device__ __forceinline__ float2 cmul(float2 a, float2 b){ return make_float2(a.x*b.x - a.y*b.y, a.x*b.y + a.y*b.x); }
__device__ __forceinline__ float2 cjmul(float2 b, float2 w){ // b * conj(w)
    return make_float2(b.x*w.x + b.y*w.y, b.y*w.x - b.x*w.y); }

// ---------------- init: twiddles + mask ranks ----------------------------------
__device__ __forceinline__ int vmaxOf(int rem){
    int vm = __float2int_rd(sqrtf((float)rem));
    while (vm*vm > rem) vm--;
    while ((vm+1)*(vm+1) <= rem) vm++;
    return vm;
}
__device__ int rankOf(int u, int v){
    int rank = 0;
    for (int up = 0; up < u; up++){
        int dup = (up < 64) ? up : up - 128;
        int rem = 900 - dup*dup;
        if (rem >= 0) rank += 2*vmaxOf(rem) + 1;
    }
    int du = (u < 64) ? u : u - 128;
    int vm = vmaxOf(900 - du*du);
    return rank + ((v <= vm) ? v : v - (128 - vm) + vm + 1);
}

__global__ void init_tables(){
    int t = blockIdx.x * blockDim.x + threadIdx.x;
    if (t <= 32){
        double ang = -6.283185307179586476925286766559 * (double)t / 128.0;
        float c = (float)cos(ang), s = (float)sin(ang);
        if (t == 0)      { g_E[0]  = make_float2(1.f, 0.f);  g_E[64] = make_float2(-1.f, 0.f); }
        else if (t == 32){ g_E[32] = make_float2(0.f, -1.f); g_E[96] = make_float2(0.f, 1.f); }
        else {
            g_E[t]       = make_float2( c,  s);
            g_E[64 - t]  = make_float2(-c,  s);
            g_E[64 + t]  = make_float2(-c, -s);
            g_E[128 - t] = make_float2( c, -s);
        }
    }
    if (t < 16384){
        int u = t >> 7, v = t & 127;
        int du = (u < 64) ? u : u - 128;
        int dv = (v < 64) ? v : v - 128;
        if (du*du + dv*dv <= 900){
            int r = rankOf(u, v);
            g_maskUV[r] = t;
            g_conjRank[r] = rankOf((128 - u) & 127, (128 - v) & 127);
        }
    }
}

// ---------------- warp-level 128-pt FFT, 4 float2 regs per lane ------------------
__device__ __forceinline__ float2 shflx(float2 v, int d){
    v.x = __shfl_xor_sync(0xffffffffu, v.x, d);
    v.y = __shfl_xor_sync(0xffffffffu, v.y, d);
    return v;
}
__device__ __forceinline__ void dif_lane_stage(float2 &r, float2 w, int lane, int d){
    float2 q = shflx(r, d);
    if (lane & d) r = cmul(csub(q, r), w);
    else          r = cadd(r, q);
}
__device__ __forceinline__ void dit_lane_stage(float2 &r, float2 w, int lane, int d){
    float2 q = shflx(r, d);
    if (lane & d) r = csub(q, cjmul(r, w));
    else          r = cadd(r, cjmul(q, w));
}

// DIF: natural-order input (lane t holds positions t, t+32, t+64, t+96);
// output in-place in bit-reversed position order.
__device__ __forceinline__ void warp_dif128(float2 &r0, float2 &r1, float2 &r2, float2 &r3,
                                            const float2* tw, int lane){
    float2 a;
    float2 w0 = tw[lane], w1 = tw[lane + 32];
    a = r0; r0 = cadd(a, r2); r2 = cmul(csub(a, r2), w0);
    a = r1; r1 = cadd(a, r3); r3 = cmul(csub(a, r3), w1);
    float2 w2 = tw[2*lane];
    a = r0; r0 = cadd(a, r1); r1 = cmul(csub(a, r1), w2);
    a = r2; r2 = cadd(a, r3); r3 = cmul(csub(a, r3), w2);
    #pragma unroll
    for (int d = 16; d >= 1; d >>= 1){
        float2 w = tw[(lane & (d-1)) * (64/d)];
        dif_lane_stage(r0, w, lane, d);
        dif_lane_stage(r1, w, lane, d);
        dif_lane_stage(r2, w, lane, d);
        dif_lane_stage(r3, w, lane, d);
    }
}

// DIT: bit-reversed-position input, natural-order output.
__device__ __forceinline__ void warp_dit128(float2 &r0, float2 &r1, float2 &r2, float2 &r3,
                                            const float2* tw, int lane){
    #pragma unroll
    for (int d = 1; d <= 16; d <<= 1){
        float2 w = tw[(lane & (d-1)) * (64/d)];
        dit_lane_stage(r0, w, lane, d);
        dit_lane_stage(r1, w, lane, d);
        dit_lane_stage(r2, w, lane, d);
        dit_lane_stage(r3, w, lane, d);
    }
    float2 t;
    float2 w2 = tw[2*lane];
    t = cjmul(r1, w2); r1 = csub(r0, t); r0 = cadd(r0, t);
    t = cjmul(r3, w2); r3 = csub(r2, t); r2 = cadd(r2, t);
    float2 w0 = tw[lane], w1 = tw[lane + 32];
    t = cjmul(r2, w0); r2 = csub(r0, t); r0 = cadd(r0, t);
    t = cjmul(r3, w1); r3 = csub(r1, t); r1 = cadd(r1, t);
}

// ---------------- forward: pack 2 real channels per complex FFT ----------------
__global__ __launch_bounds__(512) void fwd_kernel(const float* __restrict__ x, int nMask){
    extern __shared__ float2 data[];
    __shared__ float2 tw[128];
    __shared__ int s_vpos[61];
    int tid = threadIdx.x, lane = tid & 31, wid = tid >> 5;
    if (tid < 128) tw[tid] = g_E[tid];
    if (tid < 61){
        int v = (tid < 31) ? tid : tid + 67;     // v in [0,30] U [98,127]
        s_vpos[tid] = brev7(v);
    }
    int b = blockIdx.x >> 5, ip = blockIdx.x & 31;
    int i0 = 2*ip;
    const float* s0 = x + (size_t)(b*64 + i0) * 16384;
    const float* s1 = s0 + 16384;
    __syncthreads();

    // Phase A: row FFTs in registers, write bit-rev positions into tile rows
    for (int r = wid; r < 128; r += 16){
        const float* p0 = s0 + r*128;
        const float* p1 = s1 + r*128;
        float2 r0 = make_float2(p0[lane     ], p1[lane     ]);
        float2 r1 = make_float2(p0[lane + 32], p1[lane + 32]);
        float2 r2 = make_float2(p0[lane + 64], p1[lane + 64]);
        float2 r3 = make_float2(p0[lane + 96], p1[lane + 96]);
        warp_dif128(r0, r1, r2, r3, tw, lane);
        float2* row = data + r*PITCH;
        row[lane] = r0; row[lane+32] = r1; row[lane+64] = r2; row[lane+96] = r3;
    }
    __syncthreads();

    // Phase B: column FFTs, only the 61 masked columns, in place
    for (int c = wid; c < 61; c += 16){
        float2* col = data + s_vpos[c];
        float2 r0 = col[(lane     )*PITCH];
        float2 r1 = col[(lane + 32)*PITCH];
        float2 r2 = col[(lane + 64)*PITCH];
        float2 r3 = col[(lane + 96)*PITCH];
        warp_dif128(r0, r1, r2, r3, tw, lane);
        col[(lane     )*PITCH] = r0;
        col[(lane + 32)*PITCH] = r1;
        col[(lane + 64)*PITCH] = r2;
        col[(lane + 96)*PITCH] = r3;
    }
    __syncthreads();

    // Phase C: masked gather + Hermitian split; g_Xf layout [f][i*16+b]
    for (int f = tid; f < nMask; f += 512){
        int pr = g_conjRank[f];
        if (pr < f) continue;
        int uv  = g_maskUV[f];
        int uvb = g_maskUV[pr];
        float2 z  = data[brev7(uv  >> 7)*PITCH + brev7(uv  & 127)];
        float2 zc = data[brev7(uvb >> 7)*PITCH + brev7(uvb & 127)];
        float2 X0 = make_float2(0.5f*(z.x + zc.x), 0.5f*(z.y - zc.y));
        float2 X1 = make_float2(0.5f*(z.y + zc.y), 0.5f*(zc.x - z.x));
        size_t base = (size_t)f*1024 + i0*16 + b;
        g_Xf[base]      = X0;
        g_Xf[base + 16] = X1;
    }
}

// ---------------- per-frequency channel mix (primary bins only) ----------------
__global__ __launch_bounds__(256) void mix_kernel(const float* __restrict__ wgt, int nMask){
    __shared__ float4 Xs4[512];      // [i][b] as float2 pairs
    __shared__ float2 Ws[64 * 65];   // [o][i]
    __shared__ float2 c9[9];
    int f = blockIdx.x;
    int pr = g_conjRank[f];
    if (pr < f) return;
    int tid = threadIdx.x;
    int uv = g_maskUV[f];
    if (tid < 9){
        int p = tid / 3, q = tid % 3;
        c9[tid] = g_E[((uv >> 7)*p + (uv & 127)*q) & 127];
    }
    for (int j = tid; j < 512; j += 256) Xs4[j] = g_Xf4[(size_t)f*512 + j];
    __syncthreads();
    for (int oi = tid; oi < 4096; oi += 256){
        const float* w9 = wgt + oi*9;
        float2 acc = make_float2(0.f, 0.f);
        #pragma unroll
        for (int k = 0; k < 9; k++){
            float wv = w9[k];
            acc.x += wv * c9[k].x;
            acc.y += wv * c9[k].y;
        }
        Ws[(oi >> 6)*65 + (oi & 63)] = acc;
    }
    __syncthreads();
    int o  = tid & 63;
    int bb = (tid >> 6) << 2;        // 0,4,8,12
    float2 a0 = make_float2(0.f,0.f), a1 = a0, a2 = a0, a3 = a0;
    const float2* wrow = &Ws[o * 65];
    int xbase = bb >> 1;             // float4 index offset for this batch group
    #pragma unroll 8
    for (int i = 0; i < 64; i++){
        float2 w  = wrow[i];
        float4 xa = Xs4[i*8 + xbase];      // batches bb, bb+1
        float4 xb = Xs4[i*8 + xbase + 1];  // batches bb+2, bb+3
        a0.x += xa.x*w.x - xa.y*w.y;  a0.y += xa.x*w.y + xa.y*w.x;
        a1.x += xa.z*w.x - xa.w*w.y;  a1.y += xa.z*w.y + xa.w*w.x;
        a2.x += xb.x*w.x - xb.y*w.y;  a2.y += xb.x*w.y + xb.y*w.x;
        a3.x += xb.z*w.x - xb.w*w.y;  a3.y += xb.z*w.y + xb.w*w.x;
    }
    size_t bf = (size_t)f*1024, bp = (size_t)pr*1024;
    g_Yf[bf + (bb+0)*64 + o] = a0;
    g_Yf[bf + (bb+1)*64 + o] = a1;
    g_Yf[bf + (bb+2)*64 + o] = a2;
    g_Yf[bf + (bb+3)*64 + o] = a3;
    if (pr != f){
        g_Yf[bp + (bb+0)*64 + o] = make_float2(a0.x, -a0.y);
        g_Yf[bp + (bb+1)*64 + o] = make_float2(a1.x, -a1.y);
        g_Yf[bp + (bb+2)*64 + o] = make_float2(a2.x, -a2.y);
        g_Yf[bp + (bb+3)*64 + o] = make_float2(a3.x, -a3.y);
    }
}

// ---------------- inverse: pack 2 real outputs per complex IFFT ----------------
__global__ __launch_bounds__(512) void inv_kernel(float* __restrict__ out,
                                                  const float* __restrict__ bias, int nMask){
    extern __shared__ float2 data[];
    __shared__ float2 tw[128];
    __shared__ int s_vpos[61];
    int tid = threadIdx.x, lane = tid & 31, wid = tid >> 5;
    if (tid < 128) tw[tid] = g_E[tid];
    if (tid < 61){
        int v = (tid < 31) ? tid : tid + 67;
        s_vpos[tid] = brev7(v);
    }
    int b = blockIdx.x >> 5, op = blockIdx.x & 31;
    int o0 = 2*op;
    int bsrc = (b + 8) & 15;
    int osrc = (o0 + 32) & 63;
    for (int idx = tid; idx < 128*PITCH; idx += 512) data[idx] = make_float2(0.f, 0.f);
    __syncthreads();

    // scatter masked bins (bit-rev positions both dims), Z = Y0 + i*Y1
    for (int f = tid; f < nMask; f += 512){
        int uv = g_maskUV[f];
        float4 y = *(const float4*)&g_Yf4[(size_t)f*512 + (bsrc*64 + osrc)/2];
        data[brev7(uv >> 7)*PITCH + brev7(uv & 127)] = make_float2(y.x - y.w, y.y + y.z);
    }
    __syncthreads();

    // Phase B': u-transform (DIT) on the 61 masked columns, in place
    for (int c = wid; c < 61; c += 16){
        float2* col = data + s_vpos[c];
        float2 r0 = col[(lane     )*PITCH];
        float2 r1 = col[(lane + 32)*PITCH];
        float2 r2 = col[(lane + 64)*PITCH];
        float2 r3 = col[(lane + 96)*PITCH];
        warp_dit128(r0, r1, r2, r3, tw, lane);
        col[(lane     )*PITCH] = r0;
        col[(lane + 32)*PITCH] = r1;
        col[(lane + 64)*PITCH] = r2;
        col[(lane + 96)*PITCH] = r3;
    }
    __syncthreads();

    // Phase C': v-transform (DIT) per row, direct coalesced global store
    float bv0 = bias[o0], bv1 = bias[o0 + 1];
    float* d0 = out + (size_t)(b*64 + o0) * 16384;
    float* d1 = d0 + 16384;
    const float sc = 1.f / 16384.f;
    for (int r = wid; r < 128; r += 16){
        const float2* row = data + r*PITCH;
        float2 r0 = row[lane];
        float2 r1 = row[lane + 32];
        float2 r2 = row[lane + 64];
        float2 r3 = row[lane + 96];
        warp_dit128(r0, r1, r2, r3, tw, lane);
        float* q0 = d0 + r*128;
        float* q1 = d1 + r*128;
        q0[lane     ] = r0.x*sc + bv0;  q1[lane     ] = r0.y*sc + bv1;
        q0[lane + 32] = r1.x*sc + bv0;  q1[lane + 32] = r1.y*sc + bv1;
        q0[lane + 64] = r2.x*sc + bv0;  q1[lane + 64] = r2.y*sc + bv1;
        q0[lane + 96] = r3.x*sc + bv0;  q1[lane + 96] = r3.y*sc + bv1;
    }
}

// ---------------- launch --------------------------------------------------------
extern "C" void kernel_launch(void* const* d_in, const int* in_sizes, int n_in,
                              void* d_out, int out_size){
    const float* x    = (const float*)d_in[0];
    const float* wgt  = (const float*)d_in[1];
    const float* bias = (const float*)d_in[2];
    float* out = (float*)d_out;

    int nMask = 0;
    for (int u = 0; u < 128; u++){
        int du = (u < 64) ? u : u - 128;
        for (int v = 0; v < 128; v++){
            int dv = (v < 64) ? v : v - 128;
            if (du*du + dv*dv <= 900) nMask++;
        }
    }

    cudaFuncSetAttribute(fwd_kernel, cudaFuncAttributeMaxDynamicSharedMemorySize, (int)SMEM_BYTES);
    cudaFuncSetAttribute(inv_kernel, cudaFuncAttributeMaxDynamicSharedMemorySize, (int)SMEM_BYTES);

    init_tables<<<64, 256>>>();
    fwd_kernel<<<512, 512, SMEM_BYTES>>>(x, nMask);
    mix_kernel<<<nMask, 256>>>(wgt, nMask);
    inv_kernel<<<512, 512, SMEM_BYTES>>>(out, bias, nMask);
}

// round 4
// speedup vs baseline: 1.0735x; 1.0735x over previous
#include <cuda_runtime.h>

#define TP 129                                      // tile pitch (rows) for [col][row] layout
#define NCOL 61                                     // masked v-columns: [0,30] U [98,127]
#define NF_MAX 2850                                 // >= 2821 masked frequencies
#define TILE_BYTES (NCOL * TP * sizeof(float2))     // 62952 B

// ---------------- device scratch ------------------------------------------------
__device__ float2 g_E[128];                         // exp(-2*pi*i*k/128)
__device__ int    g_maskUV[NF_MAX];
__device__ int    g_conjRank[NF_MAX];
__device__ int    g_offA[NF_MAX];                   // cidx(v)*TP + brev7(u)
__device__ int    g_offB[NF_MAX];                   // same for conj bin
__device__ float4 g_Xf4[(size_t)NF_MAX * 512];      // [f][i*16+b] /2
__device__ float4 g_Yf4[(size_t)NF_MAX * 512];      // [f][b*64+o] /2
#define g_Xf ((float2*)g_Xf4)
#define g_Yf ((float2*)g_Yf4)

__device__ __forceinline__ int brev7(int x) { return (int)(__brev((unsigned)x) >> 25); }
__device__ __forceinline__ float2 cadd(float2 a, float2 b){ return make_float2(a.x+b.x, a.y+b.y); }
__device__ __forceinline__ float2 csub(float2 a, float2 b){ return make_float2(a.x-b.x, a.y-b.y); }
__device__ __forceinline__ float2 cmul(float2 a, float2 b){ return make_float2(a.x*b.x - a.y*b.y, a.x*b.y + a.y*b.x); }
__device__ __forceinline__ float2 cjmul(float2 b, float2 w){
    return make_float2(b.x*w.x + b.y*w.y, b.y*w.x - b.x*w.y); }

// ---------------- init ----------------------------------------------------------
__device__ __forceinline__ int vmaxOf(int rem){
    int vm = __float2int_rd(sqrtf((float)rem));
    while (vm*vm > rem) vm--;
    while ((vm+1)*(vm+1) <= rem) vm++;
    return vm;
}
__device__ int rankOf(int u, int v){
    int rank = 0;
    for (int up = 0; up < u; up++){
        int dup = (up < 64) ? up : up - 128;
        int rem = 900 - dup*dup;
        if (rem >= 0) rank += 2*vmaxOf(rem) + 1;
    }
    int du = (u < 64) ? u : u - 128;
    int vm = vmaxOf(900 - du*du);
    return rank + ((v <= vm) ? v : v - (128 - vm) + vm + 1);
}
__device__ __forceinline__ int cidxOf(int v){ return (v <= 30) ? v : v - 67; }

__global__ void init_tables(){
    int t = blockIdx.x * blockDim.x + threadIdx.x;
    if (t <= 32){
        double ang = -6.283185307179586476925286766559 * (double)t / 128.0;
        float c = (float)cos(ang), s = (float)sin(ang);
        if (t == 0)      { g_E[0]  = make_float2(1.f, 0.f);  g_E[64] = make_float2(-1.f, 0.f); }
        else if (t == 32){ g_E[32] = make_float2(0.f, -1.f); g_E[96] = make_float2(0.f, 1.f); }
        else {
            g_E[t]       = make_float2( c,  s);
            g_E[64 - t]  = make_float2(-c,  s);
            g_E[64 + t]  = make_float2(-c, -s);
            g_E[128 - t] = make_float2( c, -s);
        }
    }
    if (t < 16384){
        int u = t >> 7, v = t & 127;
        int du = (u < 64) ? u : u - 128;
        int dv = (v < 64) ? v : v - 128;
        if (du*du + dv*dv <= 900){
            int r = rankOf(u, v);
            int uc = (128 - u) & 127, vc = (128 - v) & 127;
            g_maskUV[r]   = t;
            g_conjRank[r] = rankOf(uc, vc);
            g_offA[r]     = cidxOf(v)  * TP + brev7(u);
            g_offB[r]     = cidxOf(vc) * TP + brev7(uc);
        }
    }
}

// ---------------- warp-level 128-pt FFT, 4 float2 regs per lane ------------------
__device__ __forceinline__ float2 shflx(float2 v, int d){
    v.x = __shfl_xor_sync(0xffffffffu, v.x, d);
    v.y = __shfl_xor_sync(0xffffffffu, v.y, d);
    return v;
}
__device__ __forceinline__ void dif_lane_stage(float2 &r, float2 w, int lane, int d){
    float2 q = shflx(r, d);
    if (lane & d) r = cmul(csub(q, r), w);
    else          r = cadd(r, q);
}
__device__ __forceinline__ void dit_lane_stage(float2 &r, float2 w, int lane, int d){
    float2 q = shflx(r, d);
    if (lane & d) r = csub(q, cjmul(r, w));
    else          r = cadd(r, cjmul(q, w));
}
// DIF: natural input (lane t holds t, t+32, t+64, t+96); bit-rev position output.
__device__ __forceinline__ void warp_dif128(float2 &r0, float2 &r1, float2 &r2, float2 &r3,
                                            const float2* tw, int lane){
    float2 a;
    float2 w0 = tw[lane], w1 = tw[lane + 32];
    a = r0; r0 = cadd(a, r2); r2 = cmul(csub(a, r2), w0);
    a = r1; r1 = cadd(a, r3); r3 = cmul(csub(a, r3), w1);
    float2 w2 = tw[2*lane];
    a = r0; r0 = cadd(a, r1); r1 = cmul(csub(a, r1), w2);
    a = r2; r2 = cadd(a, r3); r3 = cmul(csub(a, r3), w2);
    #pragma unroll
    for (int d = 16; d >= 1; d >>= 1){
        float2 w = tw[(lane & (d-1)) * (64/d)];
        dif_lane_stage(r0, w, lane, d);
        dif_lane_stage(r1, w, lane, d);
        dif_lane_stage(r2, w, lane, d);
        dif_lane_stage(r3, w, lane, d);
    }
}
// DIT: bit-rev position input, natural output.
__device__ __forceinline__ void warp_dit128(float2 &r0, float2 &r1, float2 &r2, float2 &r3,
                                            const float2* tw, int lane){
    #pragma unroll
    for (int d = 1; d <= 16; d <<= 1){
        float2 w = tw[(lane & (d-1)) * (64/d)];
        dit_lane_stage(r0, w, lane, d);
        dit_lane_stage(r1, w, lane, d);
        dit_lane_stage(r2, w, lane, d);
        dit_lane_stage(r3, w, lane, d);
    }
    float2 t;
    float2 w2 = tw[2*lane];
    t = cjmul(r1, w2); r1 = csub(r0, t); r0 = cadd(r0, t);
    t = cjmul(r3, w2); r3 = csub(r2, t); r2 = cadd(r2, t);
    float2 w0 = tw[lane], w1 = tw[lane + 32];
    t = cjmul(r2, w0); r2 = csub(r0, t); r0 = cadd(r0, t);
    t = cjmul(r3, w1); r3 = csub(r1, t); r1 = cadd(r1, t);
}

// store one bit-rev-position output into the compact tile if its frequency is masked
__device__ __forceinline__ void store_masked(float2* tile, float2 val, int p, int r){
    int v = brev7(p);
    if (v <= 30)       tile[v * TP + r]        = val;
    else if (v >= 98)  tile[(v - 67) * TP + r] = val;
}

// ---------------- forward: pack 2 real channels per complex FFT ----------------
__global__ __launch_bounds__(384, 3) void fwd_kernel(const float* __restrict__ x, int nMask){
    extern __shared__ float2 tile[];               // [NCOL][TP]
    __shared__ float2 tw[128];
    int tid = threadIdx.x, lane = tid & 31, wid = tid >> 5;
    if (tid < 128) tw[tid] = g_E[tid];
    int b = blockIdx.x >> 5, ip = blockIdx.x & 31;
    int i0 = 2*ip;
    const float* s0 = x + (size_t)(b*64 + i0) * 16384;
    const float* s1 = s0 + 16384;
    __syncthreads();

    // Phase A: row FFTs in registers; store only masked v-columns
    for (int r = wid; r < 128; r += 12){
        const float* p0 = s0 + r*128;
        const float* p1 = s1 + r*128;
        float2 r0 = make_float2(p0[lane     ], p1[lane     ]);
        float2 r1 = make_float2(p0[lane + 32], p1[lane + 32]);
        float2 r2 = make_float2(p0[lane + 64], p1[lane + 64]);
        float2 r3 = make_float2(p0[lane + 96], p1[lane + 96]);
        warp_dif128(r0, r1, r2, r3, tw, lane);
        store_masked(tile, r0, lane,      r);
        store_masked(tile, r1, lane + 32, r);
        store_masked(tile, r2, lane + 64, r);
        store_masked(tile, r3, lane + 96, r);
    }
    __syncthreads();

    // Phase B: column FFTs on the 61 compact columns
    for (int c = wid; c < NCOL; c += 12){
        float2* col = tile + c*TP;
        float2 r0 = col[lane     ];
        float2 r1 = col[lane + 32];
        float2 r2 = col[lane + 64];
        float2 r3 = col[lane + 96];
        warp_dif128(r0, r1, r2, r3, tw, lane);
        col[lane     ] = r0;
        col[lane + 32] = r1;
        col[lane + 64] = r2;
        col[lane + 96] = r3;
    }
    __syncthreads();

    // Phase C: masked gather + Hermitian split; g_Xf layout [f][i*16+b]
    for (int f = tid; f < nMask; f += 384){
        int pr = g_conjRank[f];
        if (pr < f) continue;
        float2 z  = tile[g_offA[f]];
        float2 zc = tile[g_offB[f]];
        float2 X0 = make_float2(0.5f*(z.x + zc.x), 0.5f*(z.y - zc.y));
        float2 X1 = make_float2(0.5f*(z.y + zc.y), 0.5f*(zc.x - z.x));
        size_t base = (size_t)f*1024 + i0*16 + b;
        g_Xf[base]      = X0;
        g_Xf[base + 16] = X1;
    }
}

// ---------------- per-frequency channel mix (primary bins only) ----------------
__global__ __launch_bounds__(256) void mix_kernel(const float* __restrict__ wgt, int nMask){
    __shared__ float4 Xs4[512];      // [i][b] as float2 pairs
    __shared__ float2 Ws[64 * 65];   // [o][i]
    __shared__ float2 c9[9];
    int f = blockIdx.x;
    int pr = g_conjRank[f];
    if (pr < f) return;
    int tid = threadIdx.x;
    int uv = g_maskUV[f];
    if (tid < 9){
        int p = tid / 3, q = tid % 3;
        c9[tid] = g_E[((uv >> 7)*p + (uv & 127)*q) & 127];
    }
    for (int j = tid; j < 512; j += 256) Xs4[j] = g_Xf4[(size_t)f*512 + j];
    __syncthreads();
    for (int oi = tid; oi < 4096; oi += 256){
        const float* w9 = wgt + oi*9;
        float2 acc = make_float2(0.f, 0.f);
        #pragma unroll
        for (int k = 0; k < 9; k++){
            float wv = w9[k];
            acc.x += wv * c9[k].x;
            acc.y += wv * c9[k].y;
        }
        Ws[(oi >> 6)*65 + (oi & 63)] = acc;
    }
    __syncthreads();
    int o  = tid & 63;
    int bb = (tid >> 6) << 2;
    float2 a0 = make_float2(0.f,0.f), a1 = a0, a2 = a0, a3 = a0;
    const float2* wrow = &Ws[o * 65];
    int xbase = bb >> 1;
    #pragma unroll 8
    for (int i = 0; i < 64; i++){
        float2 w  = wrow[i];
        float4 xa = Xs4[i*8 + xbase];
        float4 xb = Xs4[i*8 + xbase + 1];
        a0.x += xa.x*w.x - xa.y*w.y;  a0.y += xa.x*w.y + xa.y*w.x;
        a1.x += xa.z*w.x - xa.w*w.y;  a1.y += xa.z*w.y + xa.w*w.x;
        a2.x += xb.x*w.x - xb.y*w.y;  a2.y += xb.x*w.y + xb.y*w.x;
        a3.x += xb.z*w.x - xb.w*w.y;  a3.y += xb.z*w.y + xb.w*w.x;
    }
    size_t bf = (size_t)f*1024, bp = (size_t)pr*1024;
    g_Yf[bf + (bb+0)*64 + o] = a0;
    g_Yf[bf + (bb+1)*64 + o] = a1;
    g_Yf[bf + (bb+2)*64 + o] = a2;
    g_Yf[bf + (bb+3)*64 + o] = a3;
    if (pr != f){
        g_Yf[bp + (bb+0)*64 + o] = make_float2(a0.x, -a0.y);
        g_Yf[bp + (bb+1)*64 + o] = make_float2(a1.x, -a1.y);
        g_Yf[bp + (bb+2)*64 + o] = make_float2(a2.x, -a2.y);
        g_Yf[bp + (bb+3)*64 + o] = make_float2(a3.x, -a3.y);
    }
}

// ---------------- inverse: pack 2 real outputs per complex IFFT ----------------
__global__ __launch_bounds__(384, 3) void inv_kernel(float* __restrict__ out,
                                                     const float* __restrict__ bias, int nMask){
    extern __shared__ float2 tile[];               // [NCOL][TP]
    __shared__ float2 tw[128];
    int tid = threadIdx.x, lane = tid & 31, wid = tid >> 5;
    if (tid < 128) tw[tid] = g_E[tid];
    int b = blockIdx.x >> 5, op = blockIdx.x & 31;
    int o0 = 2*op;
    int bsrc = (b + 8) & 15;
    int osrc = (o0 + 32) & 63;
    for (int idx = tid; idx < NCOL*TP; idx += 384) tile[idx] = make_float2(0.f, 0.f);
    __syncthreads();

    // scatter masked bins; Z = Y0 + i*Y1
    for (int f = tid; f < nMask; f += 384){
        float4 y = *(const float4*)&g_Yf4[(size_t)f*512 + (bsrc*64 + osrc)/2];
        tile[g_offA[f]] = make_float2(y.x - y.w, y.y + y.z);
    }
    __syncthreads();

    // Phase B': u-transform (DIT) on the 61 compact columns
    for (int c = wid; c < NCOL; c += 12){
        float2* col = tile + c*TP;
        float2 r0 = col[lane     ];
        float2 r1 = col[lane + 32];
        float2 r2 = col[lane + 64];
        float2 r3 = col[lane + 96];
        warp_dit128(r0, r1, r2, r3, tw, lane);
        col[lane     ] = r0;
        col[lane + 32] = r1;
        col[lane + 64] = r2;
        col[lane + 96] = r3;
    }
    __syncthreads();

    // Phase C': v-transform per row; masked positions from tile, rest zero
    float bv0 = bias[o0], bv1 = bias[o0 + 1];
    float* d0 = out + (size_t)(b*64 + o0) * 16384;
    float* d1 = d0 + 16384;
    const float sc = 1.f / 16384.f;
    for (int r = wid; r < 128; r += 12){
        float2 rr[4];
        #pragma unroll
        for (int k = 0; k < 4; k++){
            int p = lane + 32*k;
            int v = brev7(p);
            float2 val = make_float2(0.f, 0.f);
            if (v <= 30)      val = tile[v * TP + r];
            else if (v >= 98) val = tile[(v - 67) * TP + r];
            rr[k] = val;
        }
        warp_dit128(rr[0], rr[1], rr[2], rr[3], tw, lane);
        float* q0 = d0 + r*128;
        float* q1 = d1 + r*128;
        q0[lane     ] = rr[0].x*sc + bv0;  q1[lane     ] = rr[0].y*sc + bv1;
        q0[lane + 32] = rr[1].x*sc + bv0;  q1[lane + 32] = rr[1].y*sc + bv1;
        q0[lane + 64] = rr[2].x*sc + bv0;  q1[lane + 64] = rr[2].y*sc + bv1;
        q0[lane + 96] = rr[3].x*sc + bv0;  q1[lane + 96] = rr[3].y*sc + bv1;
    }
}

// ---------------- launch --------------------------------------------------------
extern "C" void kernel_launch(void* const* d_in, const int* in_sizes, int n_in,
                              void* d_out, int out_size){
    const float* x    = (const float*)d_in[0];
    const float* wgt  = (const float*)d_in[1];
    const float* bias = (const float*)d_in[2];
    float* out = (float*)d_out;

    int nMask = 0;
    for (int u = 0; u < 128; u++){
        int du = (u < 64) ? u : u - 128;
        for (int v = 0; v < 128; v++){
            int dv = (v < 64) ? v : v - 128;
            if (du*du + dv*dv <= 900) nMask++;
        }
    }

    cudaFuncSetAttribute(fwd_kernel, cudaFuncAttributeMaxDynamicSharedMemorySize, (int)TILE_BYTES);
    cudaFuncSetAttribute(inv_kernel, cudaFuncAttributeMaxDynamicSharedMemorySize, (int)TILE_BYTES);

    init_tables<<<64, 256>>>();
    fwd_kernel<<<512, 384, TILE_BYTES>>>(x, nMask);
    mix_kernel<<<nMask, 256>>>(wgt, nMask);
    inv_kernel<<<512, 384, TILE_BYTES>>>(out, bias, nMask);
}